// round 5
// baseline (speedup 1.0000x reference)
#include <cuda_runtime.h>
#include <cuda_fp16.h>
#include <cstdint>

// LoRAConv1D: out = x @ W + b + 4.0 * (x @ A) @ B
//   x:[8192,1600]f32  W:[1600,4800]f32  b:[4800]  A:[1600,8]  B:[8,4800]
//
// Single-product fp16 tensor path (sm_103, non-'a' target):
//  1) W' = W + 4*A@B rounded fp16, transposed [N,K]
//  2) x rounded fp16 [M,K]
//  3) out = fp16(x) * fp16(W') + b with fp32 accum (mma.sync m16n8k16)
//     rel err ~ sqrt(2)*2^-11/sqrt(3) ~ 3e-4 < 1e-3 (calibrated R4: 2.07e-4
//     from W rounding alone).
//  BM=256 BN=96 BK=32, 4-stage cp.async, swizzled ldmatrix, warp tile 64x48.

#define M_TOT 8192
#define N_TOT 4800
#define K_TOT 1600
#define RANK  8

#define BM 256
#define BN 96
#define BK 32
#define KITERS (K_TOT / BK)        // 50
#define STAGES 4

// stage layout (bytes): A[256*64] B[96*64]
#define A_OFF 0
#define B_OFF 16384
#define STAGE_BYTES 22528
#define SMEM_TOTAL (STAGES * STAGE_BYTES)   // 90112

// ---------------- device scratch (static, alloc-free) ----------------------
__device__ __half g_x[(size_t)M_TOT * K_TOT];    // fp16 x
__device__ __half g_w[(size_t)N_TOT * K_TOT];    // [N,K] fused fp16 weight

// ---------------- helpers ---------------------------------------------------
__device__ __forceinline__ uint32_t smem_u32(const void* p) {
    uint32_t a;
    asm("{ .reg .u64 t; cvta.to.shared.u64 t, %1; cvt.u32.u64 %0, t; }"
        : "=r"(a) : "l"(p));
    return a;
}
// swizzled byte offset in a tile (row pitch 64B, 16B chunks), conflict-free
// for both ldmatrix phases and the cp.async writes.
__device__ __forceinline__ uint32_t swz(int row, int ch) {
    return (uint32_t)(row * 64 + 16 * (ch ^ (row & 3) ^ ((row >> 2) & 1)));
}
__device__ __forceinline__ void cp16(uint32_t dst, const void* src) {
    asm volatile("cp.async.cg.shared.global [%0], [%1], 16;"
                 :: "r"(dst), "l"(src));
}
#define CP_COMMIT() asm volatile("cp.async.commit_group;")
#define CP_WAIT2()  asm volatile("cp.async.wait_group 2;")

__device__ __forceinline__ void ldm_x4(uint32_t* r, uint32_t addr) {
    asm volatile("ldmatrix.sync.aligned.m8n8.x4.shared.b16 {%0,%1,%2,%3}, [%4];"
                 : "=r"(r[0]), "=r"(r[1]), "=r"(r[2]), "=r"(r[3]) : "r"(addr));
}
__device__ __forceinline__ void mma_f16(float* d, const uint32_t* a,
                                        const uint32_t* b) {
    asm volatile(
        "mma.sync.aligned.m16n8k16.row.col.f32.f16.f16.f32 "
        "{%0,%1,%2,%3}, {%4,%5,%6,%7}, {%8,%9}, {%0,%1,%2,%3};"
        : "+f"(d[0]), "+f"(d[1]), "+f"(d[2]), "+f"(d[3])
        : "r"(a[0]), "r"(a[1]), "r"(a[2]), "r"(a[3]), "r"(b[0]), "r"(b[1]));
}

// ---------------- kernel 1: x -> fp16 ---------------------------------------
__global__ void convert_x_kernel(const float* __restrict__ x) {
    size_t base = ((size_t)blockIdx.x * blockDim.x + threadIdx.x) * 8;
    if (base >= (size_t)M_TOT * K_TOT) return;
    float v[8];
    *(float4*)(v)     = *(const float4*)(x + base);
    *(float4*)(v + 4) = *(const float4*)(x + base + 4);
    uint4 ph;
    __half* hp = (__half*)&ph;
#pragma unroll
    for (int j = 0; j < 8; j++) hp[j] = __float2half_rn(v[j]);
    *(uint4*)((char*)g_x + base * 2) = ph;
}

// ---------------- kernel 2: W' = W + 4*A@B -> fp16, transposed [N,K] --------
__global__ void fuse_w_kernel(const float* __restrict__ W,
                              const float* __restrict__ A,
                              const float* __restrict__ Bl) {
    __shared__ __half sh[32][33];
    const int n0 = blockIdx.x * 32, k0 = blockIdx.y * 32;
    const int tx = threadIdx.x & 31, ty = threadIdx.x >> 5;   // 32 x 8
#pragma unroll
    for (int rr = 0; rr < 4; rr++) {
        int k = k0 + ty + rr * 8, n = n0 + tx;
        float acc = W[(size_t)k * N_TOT + n];
#pragma unroll
        for (int r = 0; r < RANK; r++)
            acc += 4.0f * A[k * RANK + r] * Bl[r * N_TOT + n];
        sh[ty + rr * 8][tx] = __float2half_rn(acc);
    }
    __syncthreads();
#pragma unroll
    for (int rr = 0; rr < 4; rr++) {
        int n = n0 + ty + rr * 8, k = k0 + tx;
        g_w[(size_t)n * K_TOT + k] = sh[tx][ty + rr * 8];
    }
}

// ---------------- kernel 3: fp16 mma.sync GEMM ------------------------------
// 8 warps: wm = wid&3 (64-row slab), wn = wid>>2 (48-col slab).
// Warp tile 64x48: mt=4 (m16), nt=6 (n8) -> acc[4][6][4].
__global__ __launch_bounds__(256, 1)
void gemm_kernel(const float* __restrict__ bias, float* __restrict__ out) {
    extern __shared__ char smem[];
    const uint32_t sb = smem_u32(smem);
    const int tid = threadIdx.x, lane = tid & 31, wid = tid >> 5;
    const int wm = wid & 3;
    const int wn = wid >> 2;
    const int m0 = blockIdx.y * BM;
    const int n0 = blockIdx.x * BN;

    // ---- ldmatrix address precompute (kk=1 is ^32 on the offset) ----
    uint32_t aOff[4];
#pragma unroll
    for (int mt = 0; mt < 4; mt++) {
        int row = wm * 64 + mt * 16 + (lane & 15);
        aOff[mt] = A_OFF + swz(row, lane >> 4);
    }
    // B: 3 x4-loads per kk; pair p covers nt = 2p (regs 0,1) and 2p+1 (2,3).
    uint32_t bOff[3];
#pragma unroll
    for (int p = 0; p < 3; p++) {
        int row = wn * 48 + (2 * p + ((lane >> 4) & 1)) * 8 + (lane & 7);
        bOff[p] = B_OFF + swz(row, (lane >> 3) & 1);
    }

    float acc[4][6][4];
#pragma unroll
    for (int i = 0; i < 4; i++)
#pragma unroll
        for (int j = 0; j < 6; j++)
#pragma unroll
            for (int k = 0; k < 4; k++) acc[i][j][k] = 0.0f;

    // ---- stage loader: A 1024 chunks + B 384 chunks of 16B -----------------
    auto load_stage = [&](int s, int k0) {
        const uint32_t st = sb + s * STAGE_BYTES;
#pragma unroll
        for (int i = 0; i < 4; i++) {
            int idx = tid + i * 256;
            int row = idx >> 2, ch = idx & 3;
            cp16(st + A_OFF + swz(row, ch),
                 g_x + (size_t)(m0 + row) * K_TOT + k0 + ch * 8);
        }
        {
            int row = tid >> 2, ch = tid & 3;
            cp16(st + B_OFF + swz(row, ch),
                 g_w + (size_t)(n0 + row) * K_TOT + k0 + ch * 8);
            if (tid < 128) {
                int idx = tid + 256;
                row = idx >> 2; ch = idx & 3;
                cp16(st + B_OFF + swz(row, ch),
                     g_w + (size_t)(n0 + row) * K_TOT + k0 + ch * 8);
            }
        }
    };

    // ---- prologue: fill 3 stages ----
#pragma unroll
    for (int s = 0; s < 3; s++) { load_stage(s, s * BK); CP_COMMIT(); }

    // ---- mainloop ----
    for (int t = 0; t < KITERS; t++) {
        CP_WAIT2();
        __syncthreads();             // stage t ready; all warps done with t-1

        if (t + 3 < KITERS) load_stage((t + 3) & 3, (t + 3) * BK);
        CP_COMMIT();

        const uint32_t st = sb + (t & 3) * STAGE_BYTES;
#pragma unroll
        for (int kk = 0; kk < 2; kk++) {
            const uint32_t kx = kk ? 32u : 0u;
            uint32_t a[4][4];
#pragma unroll
            for (int mt = 0; mt < 4; mt++)
                ldm_x4(a[mt], st + (aOff[mt] ^ kx));
            uint32_t b[3][4];
#pragma unroll
            for (int p = 0; p < 3; p++)
                ldm_x4(b[p], st + (bOff[p] ^ kx));
#pragma unroll
            for (int mt = 0; mt < 4; mt++)
#pragma unroll
                for (int p = 0; p < 3; p++) {
                    mma_f16(acc[mt][2 * p],     a[mt], &b[p][0]);
                    mma_f16(acc[mt][2 * p + 1], a[mt], &b[p][2]);
                }
        }
    }

    // ---- epilogue: add bias, float2 stores ----
    const int r0 = lane >> 2, c0 = (lane & 3) * 2;
#pragma unroll
    for (int mt = 0; mt < 4; mt++)
#pragma unroll
        for (int nt = 0; nt < 6; nt++) {
            const int col = n0 + wn * 48 + nt * 8 + c0;
            const float bx = bias[col], by = bias[col + 1];
#pragma unroll
            for (int h = 0; h < 2; h++) {
                const int row = m0 + wm * 64 + mt * 16 + r0 + h * 8;
                float2 v;
                v.x = acc[mt][nt][h * 2 + 0] + bx;
                v.y = acc[mt][nt][h * 2 + 1] + by;
                *(float2*)(out + (size_t)row * N_TOT + col) = v;
            }
        }
}

// ---------------------------------------------------------------------------
extern "C" void kernel_launch(void* const* d_in, const int* in_sizes, int n_in,
                              void* d_out, int out_size) {
    const float* x  = (const float*)d_in[0];
    const float* W  = (const float*)d_in[1];
    const float* b  = (const float*)d_in[2];
    const float* lA = (const float*)d_in[3];
    const float* lB = (const float*)d_in[4];
    float* out = (float*)d_out;
    (void)in_sizes; (void)n_in; (void)out_size;

    {   // x -> fp16
        size_t total = (size_t)M_TOT * K_TOT / 8;
        convert_x_kernel<<<(unsigned)((total + 255) / 256), 256>>>(x);
    }
    {   // fuse LoRA + round + transpose W
        dim3 grid(N_TOT / 32, K_TOT / 32);
        fuse_w_kernel<<<grid, 256>>>(W, lA, lB);
    }
    {   // fp16 tensor-core GEMM
        cudaFuncSetAttribute(gemm_kernel,
                             cudaFuncAttributeMaxDynamicSharedMemorySize,
                             SMEM_TOTAL);
        dim3 grid(N_TOT / BN, M_TOT / BM);   // (50, 32)
        gemm_kernel<<<grid, 256, SMEM_TOTAL>>>(b, out);
    }
}

// round 6
// speedup vs baseline: 1.7695x; 1.7695x over previous
#include <cuda_runtime.h>
#include <cuda_fp16.h>
#include <cstdint>

// LoRAConv1D: out = x @ W + b + 4.0 * (x @ A) @ B
//   x:[8192,1600]f32  W:[1600,4800]f32  b:[4800]  A:[1600,8]  B:[8,4800]
//
// Single-product fp16 tensor path (sm_103 non-'a' target):
//  1) W' = W + 4*A@B rounded fp16, transposed [N,K], N padded 4800->4864
//  2) x rounded fp16 [M,K]
//  3) out = fp16(x)*fp16(W') + b, fp32 accum via mma.sync m16n8k16
//     (R4/R5-calibrated rel err ~2.9e-4 < 1e-3)
//  GEMM: BM=256 BN=128 BK=32, 512 threads (16 warps, 4/SMSP), warp tile
//  64x32, 4-stage cp.async, swizzled ldmatrix.

#define M_TOT 8192
#define N_TOT 4800
#define N_PAD 4864
#define K_TOT 1600
#define RANK  8

#define BM 256
#define BN 128
#define BK 32
#define KITERS (K_TOT / BK)        // 50

// stage layout (bytes): A[256*64] B[128*64]
#define A_OFF 0
#define B_OFF 16384
#define STAGE_BYTES 24576
#define SMEM_TOTAL (4 * STAGE_BYTES)   // 98304

// ---------------- device scratch (static, alloc-free) ----------------------
__device__ __half g_x[(size_t)M_TOT * K_TOT];    // fp16 x
__device__ __half g_w[(size_t)N_PAD * K_TOT];    // [N_PAD,K] fp16 W' (pad=0)

// ---------------- helpers ---------------------------------------------------
__device__ __forceinline__ uint32_t smem_u32(const void* p) {
    uint32_t a;
    asm("{ .reg .u64 t; cvta.to.shared.u64 t, %1; cvt.u32.u64 %0, t; }"
        : "=r"(a) : "l"(p));
    return a;
}
// swizzled byte offset in a tile (row pitch 64B, 16B chunks); conflict-free
// for cp.async writes and both ldmatrix phases.
__device__ __forceinline__ uint32_t swz(int row, int ch) {
    return (uint32_t)(row * 64 + 16 * (ch ^ (row & 3) ^ ((row >> 2) & 1)));
}
__device__ __forceinline__ void cp16(uint32_t dst, const void* src) {
    asm volatile("cp.async.cg.shared.global [%0], [%1], 16;"
                 :: "r"(dst), "l"(src));
}
#define CP_COMMIT() asm volatile("cp.async.commit_group;")
#define CP_WAIT2()  asm volatile("cp.async.wait_group 2;")

__device__ __forceinline__ void ldm_x4(uint32_t* r, uint32_t addr) {
    asm volatile("ldmatrix.sync.aligned.m8n8.x4.shared.b16 {%0,%1,%2,%3}, [%4];"
                 : "=r"(r[0]), "=r"(r[1]), "=r"(r[2]), "=r"(r[3]) : "r"(addr));
}
__device__ __forceinline__ void mma_f16(float* d, const uint32_t* a,
                                        const uint32_t* b) {
    asm volatile(
        "mma.sync.aligned.m16n8k16.row.col.f32.f16.f16.f32 "
        "{%0,%1,%2,%3}, {%4,%5,%6,%7}, {%8,%9}, {%0,%1,%2,%3};"
        : "+f"(d[0]), "+f"(d[1]), "+f"(d[2]), "+f"(d[3])
        : "r"(a[0]), "r"(a[1]), "r"(a[2]), "r"(a[3]), "r"(b[0]), "r"(b[1]));
}

// ---------------- kernel 1: x -> fp16 ---------------------------------------
__global__ void convert_x_kernel(const float* __restrict__ x) {
    size_t base = ((size_t)blockIdx.x * blockDim.x + threadIdx.x) * 8;
    if (base >= (size_t)M_TOT * K_TOT) return;
    float v[8];
    *(float4*)(v)     = *(const float4*)(x + base);
    *(float4*)(v + 4) = *(const float4*)(x + base + 4);
    uint4 ph;
    __half* hp = (__half*)&ph;
#pragma unroll
    for (int j = 0; j < 8; j++) hp[j] = __float2half_rn(v[j]);
    *(uint4*)((char*)g_x + base * 2) = ph;
}

// ---------------- kernel 2: W' = W + 4*A@B -> fp16, transposed [N_PAD,K] ----
__global__ void fuse_w_kernel(const float* __restrict__ W,
                              const float* __restrict__ A,
                              const float* __restrict__ Bl) {
    __shared__ __half sh[32][33];
    const int n0 = blockIdx.x * 32, k0 = blockIdx.y * 32;
    const int tx = threadIdx.x & 31, ty = threadIdx.x >> 5;   // 32 x 8
#pragma unroll
    for (int rr = 0; rr < 4; rr++) {
        int k = k0 + ty + rr * 8, n = n0 + tx;
        float acc = W[(size_t)k * N_TOT + n];
#pragma unroll
        for (int r = 0; r < RANK; r++)
            acc += 4.0f * A[k * RANK + r] * Bl[r * N_TOT + n];
        sh[ty + rr * 8][tx] = __float2half_rn(acc);
    }
    __syncthreads();
#pragma unroll
    for (int rr = 0; rr < 4; rr++) {
        int n = n0 + ty + rr * 8, k = k0 + tx;
        g_w[(size_t)n * K_TOT + k] = sh[tx][ty + rr * 8];
    }
}

// ---------------- kernel 3: fp16 mma.sync GEMM ------------------------------
// 16 warps: wm = wid&3 (64-row slab), wn = wid>>2 (32-col slab).
// Warp tile 64x32: mt=4 (m16), nt=4 (n8) -> acc[4][4][4] = 64 regs.
__global__ __launch_bounds__(512, 1)
void gemm_kernel(const float* __restrict__ bias, float* __restrict__ out) {
    extern __shared__ char smem[];
    const uint32_t sb = smem_u32(smem);
    const int tid = threadIdx.x, lane = tid & 31, wid = tid >> 5;
    const int wm = wid & 3;
    const int wn = wid >> 2;
    const int m0 = blockIdx.y * BM;
    const int n0 = blockIdx.x * BN;

    // ---- ldmatrix address precompute (kk=1 is ^32 on the offset) ----
    uint32_t aOff[4];
#pragma unroll
    for (int mt = 0; mt < 4; mt++) {
        int row = wm * 64 + mt * 16 + (lane & 15);
        aOff[mt] = A_OFF + swz(row, lane >> 4);
    }
    // B: 2 x4-loads per kk; pair p covers nt = 2p (regs 0,1) and 2p+1 (2,3).
    uint32_t bOff[2];
#pragma unroll
    for (int p = 0; p < 2; p++) {
        int row = wn * 32 + (2 * p + ((lane >> 4) & 1)) * 8 + (lane & 7);
        bOff[p] = B_OFF + swz(row, (lane >> 3) & 1);
    }

    float acc[4][4][4];
#pragma unroll
    for (int i = 0; i < 4; i++)
#pragma unroll
        for (int j = 0; j < 4; j++)
#pragma unroll
            for (int k = 0; k < 4; k++) acc[i][j][k] = 0.0f;

    // ---- stage loader: A 1024 + B 512 chunks of 16B over 512 threads ------
    auto load_stage = [&](int s, int k0) {
        const uint32_t st = sb + s * STAGE_BYTES;
#pragma unroll
        for (int i = 0; i < 2; i++) {
            int idx = tid + i * 512;
            int row = idx >> 2, ch = idx & 3;
            cp16(st + A_OFF + swz(row, ch),
                 g_x + (size_t)(m0 + row) * K_TOT + k0 + ch * 8);
        }
        {
            int row = tid >> 2, ch = tid & 3;
            cp16(st + B_OFF + swz(row, ch),
                 g_w + (size_t)(n0 + row) * K_TOT + k0 + ch * 8);
        }
    };

    // ---- prologue: fill 3 stages ----
#pragma unroll
    for (int s = 0; s < 3; s++) { load_stage(s, s * BK); CP_COMMIT(); }

    // ---- mainloop ----
    for (int t = 0; t < KITERS; t++) {
        CP_WAIT2();
        __syncthreads();             // stage t ready; all warps done with t-1

        if (t + 3 < KITERS) load_stage((t + 3) & 3, (t + 3) * BK);
        CP_COMMIT();

        const uint32_t st = sb + (t & 3) * STAGE_BYTES;
#pragma unroll
        for (int kk = 0; kk < 2; kk++) {
            const uint32_t kx = kk ? 32u : 0u;
            uint32_t a[4][4];
#pragma unroll
            for (int mt = 0; mt < 4; mt++)
                ldm_x4(a[mt], st + (aOff[mt] ^ kx));
            uint32_t b[2][4];
#pragma unroll
            for (int p = 0; p < 2; p++)
                ldm_x4(b[p], st + (bOff[p] ^ kx));
#pragma unroll
            for (int mt = 0; mt < 4; mt++)
#pragma unroll
                for (int p = 0; p < 2; p++) {
                    mma_f16(acc[mt][2 * p],     a[mt], &b[p][0]);
                    mma_f16(acc[mt][2 * p + 1], a[mt], &b[p][2]);
                }
        }
    }

    // ---- epilogue: add bias, float2 stores (guard N edge: pad 4800..4863) --
    const int r0 = lane >> 2, c0 = (lane & 3) * 2;
#pragma unroll
    for (int mt = 0; mt < 4; mt++)
#pragma unroll
        for (int nt = 0; nt < 4; nt++) {
            const int col = n0 + wn * 32 + nt * 8 + c0;
            if (col < N_TOT) {
                const float bx = bias[col], by = bias[col + 1];
#pragma unroll
                for (int h = 0; h < 2; h++) {
                    const int row = m0 + wm * 64 + mt * 16 + r0 + h * 8;
                    float2 v;
                    v.x = acc[mt][nt][h * 2 + 0] + bx;
                    v.y = acc[mt][nt][h * 2 + 1] + by;
                    *(float2*)(out + (size_t)row * N_TOT + col) = v;
                }
            }
        }
}

// ---------------------------------------------------------------------------
extern "C" void kernel_launch(void* const* d_in, const int* in_sizes, int n_in,
                              void* d_out, int out_size) {
    const float* x  = (const float*)d_in[0];
    const float* W  = (const float*)d_in[1];
    const float* b  = (const float*)d_in[2];
    const float* lA = (const float*)d_in[3];
    const float* lB = (const float*)d_in[4];
    float* out = (float*)d_out;
    (void)in_sizes; (void)n_in; (void)out_size;

    {   // x -> fp16
        size_t total = (size_t)M_TOT * K_TOT / 8;
        convert_x_kernel<<<(unsigned)((total + 255) / 256), 256>>>(x);
    }
    {   // fuse LoRA + round + transpose W (pad rows 4800..4863 stay zero)
        dim3 grid(N_TOT / 32, K_TOT / 32);
        fuse_w_kernel<<<grid, 256>>>(W, lA, lB);
    }
    {   // fp16 tensor-core GEMM
        cudaFuncSetAttribute(gemm_kernel,
                             cudaFuncAttributeMaxDynamicSharedMemorySize,
                             SMEM_TOTAL);
        dim3 grid(N_PAD / BN, M_TOT / BM);   // (38, 32)
        gemm_kernel<<<grid, 512, SMEM_TOTAL>>>(b, out);
    }
}

// round 7
// speedup vs baseline: 1.8439x; 1.0420x over previous
#include <cuda_runtime.h>
#include <cuda_fp16.h>
#include <cstdint>

// LoRAConv1D: out = x @ W + b + 4.0 * (x @ A) @ B
//   x:[8192,1600]f32  W:[1600,4800]f32  b:[4800]  A:[1600,8]  B:[8,4800]
//
// Single-product fp16 tensor path (sm_103 non-'a' target):
//  1) W' = W + 4*A@B rounded fp16, transposed [N,K], N padded 4800->4864
//  2) x rounded fp16 [M,K]
//  3) out = fp16(x)*fp16(W') + b, fp32 accum via mma.sync m16n8k16
//     (calibrated rel err 2.93e-4 < 1e-3)
//  GEMM: BM=256 BN=128 BK=64, 512 threads (16 warps), warp tile 64x32,
//  3-stage cp.async (48KB/stage), 128B-pitch SW128 swizzle.

#define M_TOT 8192
#define N_TOT 4800
#define N_PAD 4864
#define K_TOT 1600
#define RANK  8

#define BM 256
#define BN 128
#define BK 64
#define KITERS (K_TOT / BK)        // 25

// stage layout (bytes): A[256*128] B[128*128]
#define A_OFF 0
#define B_OFF 32768
#define STAGE_BYTES 49152
#define SMEM_TOTAL (3 * STAGE_BYTES)   // 147456

// ---------------- device scratch (static, alloc-free) ----------------------
__device__ __half g_x[(size_t)M_TOT * K_TOT];    // fp16 x
__device__ __half g_w[(size_t)N_PAD * K_TOT];    // [N_PAD,K] fp16 W' (pad=0)

// ---------------- helpers ---------------------------------------------------
__device__ __forceinline__ uint32_t smem_u32(const void* p) {
    uint32_t a;
    asm("{ .reg .u64 t; cvta.to.shared.u64 t, %1; cvt.u32.u64 %0, t; }"
        : "=r"(a) : "l"(p));
    return a;
}
// 128B-pitch SW128 swizzle: 16B chunk ch of row -> ch ^ (row & 7).
// Conflict-free for cp.async row writes and ldmatrix column reads.
__device__ __forceinline__ uint32_t swz128(int row, int ch) {
    return (uint32_t)(row * 128 + 16 * (ch ^ (row & 7)));
}
__device__ __forceinline__ void cp16(uint32_t dst, const void* src) {
    asm volatile("cp.async.cg.shared.global [%0], [%1], 16;"
                 :: "r"(dst), "l"(src));
}
#define CP_COMMIT() asm volatile("cp.async.commit_group;")
#define CP_WAIT1()  asm volatile("cp.async.wait_group 1;")

__device__ __forceinline__ void ldm_x4(uint32_t* r, uint32_t addr) {
    asm volatile("ldmatrix.sync.aligned.m8n8.x4.shared.b16 {%0,%1,%2,%3}, [%4];"
                 : "=r"(r[0]), "=r"(r[1]), "=r"(r[2]), "=r"(r[3]) : "r"(addr));
}
__device__ __forceinline__ void mma_f16(float* d, const uint32_t* a,
                                        const uint32_t* b) {
    asm volatile(
        "mma.sync.aligned.m16n8k16.row.col.f32.f16.f16.f32 "
        "{%0,%1,%2,%3}, {%4,%5,%6,%7}, {%8,%9}, {%0,%1,%2,%3};"
        : "+f"(d[0]), "+f"(d[1]), "+f"(d[2]), "+f"(d[3])
        : "r"(a[0]), "r"(a[1]), "r"(a[2]), "r"(a[3]), "r"(b[0]), "r"(b[1]));
}

// ---------------- kernel 1: x -> fp16 ---------------------------------------
__global__ void convert_x_kernel(const float* __restrict__ x) {
    size_t base = ((size_t)blockIdx.x * blockDim.x + threadIdx.x) * 8;
    if (base >= (size_t)M_TOT * K_TOT) return;
    float v[8];
    *(float4*)(v)     = *(const float4*)(x + base);
    *(float4*)(v + 4) = *(const float4*)(x + base + 4);
    uint4 ph;
    __half* hp = (__half*)&ph;
#pragma unroll
    for (int j = 0; j < 8; j++) hp[j] = __float2half_rn(v[j]);
    *(uint4*)((char*)g_x + base * 2) = ph;
}

// ---------------- kernel 2: W' = W + 4*A@B -> fp16, transposed [N_PAD,K] ----
__global__ void fuse_w_kernel(const float* __restrict__ W,
                              const float* __restrict__ A,
                              const float* __restrict__ Bl) {
    __shared__ __half sh[32][33];
    const int n0 = blockIdx.x * 32, k0 = blockIdx.y * 32;
    const int tx = threadIdx.x & 31, ty = threadIdx.x >> 5;   // 32 x 8
#pragma unroll
    for (int rr = 0; rr < 4; rr++) {
        int k = k0 + ty + rr * 8, n = n0 + tx;
        float acc = W[(size_t)k * N_TOT + n];
#pragma unroll
        for (int r = 0; r < RANK; r++)
            acc += 4.0f * A[k * RANK + r] * Bl[r * N_TOT + n];
        sh[ty + rr * 8][tx] = __float2half_rn(acc);
    }
    __syncthreads();
#pragma unroll
    for (int rr = 0; rr < 4; rr++) {
        int n = n0 + ty + rr * 8, k = k0 + tx;
        g_w[(size_t)n * K_TOT + k] = sh[tx][ty + rr * 8];
    }
}

// ---------------- kernel 3: fp16 mma.sync GEMM ------------------------------
// 16 warps: wm = wid&3 (64-row slab), wn = wid>>2 (32-col slab).
// Warp tile 64x32: mt=4 (m16), nt=4 (n8) -> acc[4][4][4] = 64 regs.
__global__ __launch_bounds__(512, 1)
void gemm_kernel(const float* __restrict__ bias, float* __restrict__ out) {
    extern __shared__ char smem[];
    const uint32_t sb = smem_u32(smem);
    const int tid = threadIdx.x, lane = tid & 31, wid = tid >> 5;
    const int wm = wid & 3;
    const int wn = wid >> 2;
    const int m0 = blockIdx.y * BM;
    const int n0 = blockIdx.x * BN;
    const uint32_t l7 = lane & 7;

    // ---- fragment base addresses (row*128); chunk XOR applied per kk ----
    uint32_t aBase[4];
#pragma unroll
    for (int mt = 0; mt < 4; mt++)
        aBase[mt] = A_OFF + (uint32_t)(wm * 64 + mt * 16 + (lane & 15)) * 128;
    uint32_t bBase[2];
#pragma unroll
    for (int p = 0; p < 2; p++)
        bBase[p] = B_OFF +
            (uint32_t)(wn * 32 + (2 * p + ((lane >> 4) & 1)) * 8 + l7) * 128;
    const uint32_t aSel = lane >> 4;          // A k-half from bit 4
    const uint32_t bSel = (lane >> 3) & 1;    // B k-half from bit 3

    float acc[4][4][4];
#pragma unroll
    for (int i = 0; i < 4; i++)
#pragma unroll
        for (int j = 0; j < 4; j++)
#pragma unroll
            for (int k = 0; k < 4; k++) acc[i][j][k] = 0.0f;

    // ---- stage loader: A 2048 + B 1024 chunks of 16B over 512 threads -----
    auto load_stage = [&](int s, int k0) {
        const uint32_t st = sb + s * STAGE_BYTES;
#pragma unroll
        for (int i = 0; i < 4; i++) {
            int idx = tid + i * 512;
            int row = idx >> 3, ch = idx & 7;
            cp16(st + A_OFF + swz128(row, ch),
                 g_x + (size_t)(m0 + row) * K_TOT + k0 + ch * 8);
        }
#pragma unroll
        for (int i = 0; i < 2; i++) {
            int idx = tid + i * 512;
            int row = idx >> 3, ch = idx & 7;
            cp16(st + B_OFF + swz128(row, ch),
                 g_w + (size_t)(n0 + row) * K_TOT + k0 + ch * 8);
        }
    };

    // ---- prologue: fill 2 stages ----
    load_stage(0, 0);       CP_COMMIT();
    load_stage(1, BK);      CP_COMMIT();

    // ---- mainloop ----
    int cur = 0, nxt = 2;
    for (int t = 0; t < KITERS; t++) {
        CP_WAIT1();
        __syncthreads();             // stage t ready; all warps done with t-1

        if (t + 2 < KITERS) load_stage(nxt, (t + 2) * BK);
        CP_COMMIT();

        const uint32_t st = sb + cur * STAGE_BYTES;
#pragma unroll
        for (int kk = 0; kk < 4; kk++) {
            const uint32_t xa = 16u * (((uint32_t)(kk * 2) + aSel) ^ l7);
            const uint32_t xb = 16u * (((uint32_t)(kk * 2) + bSel) ^ l7);
            uint32_t a[4][4];
#pragma unroll
            for (int mt = 0; mt < 4; mt++)
                ldm_x4(a[mt], st + aBase[mt] + xa);
            uint32_t b[2][4];
#pragma unroll
            for (int p = 0; p < 2; p++)
                ldm_x4(b[p], st + bBase[p] + xb);
#pragma unroll
            for (int mt = 0; mt < 4; mt++)
#pragma unroll
                for (int p = 0; p < 2; p++) {
                    mma_f16(acc[mt][2 * p],     a[mt], &b[p][0]);
                    mma_f16(acc[mt][2 * p + 1], a[mt], &b[p][2]);
                }
        }
        cur = (cur == 2) ? 0 : cur + 1;
        nxt = (nxt == 2) ? 0 : nxt + 1;
    }

    // ---- epilogue: add bias, float2 stores (guard N edge: pad 4800..4863) --
    const int r0 = lane >> 2, c0 = (lane & 3) * 2;
#pragma unroll
    for (int mt = 0; mt < 4; mt++)
#pragma unroll
        for (int nt = 0; nt < 4; nt++) {
            const int col = n0 + wn * 32 + nt * 8 + c0;
            if (col < N_TOT) {
                const float bx = bias[col], by = bias[col + 1];
#pragma unroll
                for (int h = 0; h < 2; h++) {
                    const int row = m0 + wm * 64 + mt * 16 + r0 + h * 8;
                    float2 v;
                    v.x = acc[mt][nt][h * 2 + 0] + bx;
                    v.y = acc[mt][nt][h * 2 + 1] + by;
                    *(float2*)(out + (size_t)row * N_TOT + col) = v;
                }
            }
        }
}

// ---------------------------------------------------------------------------
extern "C" void kernel_launch(void* const* d_in, const int* in_sizes, int n_in,
                              void* d_out, int out_size) {
    const float* x  = (const float*)d_in[0];
    const float* W  = (const float*)d_in[1];
    const float* b  = (const float*)d_in[2];
    const float* lA = (const float*)d_in[3];
    const float* lB = (const float*)d_in[4];
    float* out = (float*)d_out;
    (void)in_sizes; (void)n_in; (void)out_size;

    {   // x -> fp16
        size_t total = (size_t)M_TOT * K_TOT / 8;
        convert_x_kernel<<<(unsigned)((total + 255) / 256), 256>>>(x);
    }
    {   // fuse LoRA + round + transpose W (pad rows 4800..4863 stay zero)
        dim3 grid(N_TOT / 32, K_TOT / 32);
        fuse_w_kernel<<<grid, 256>>>(W, lA, lB);
    }
    {   // fp16 tensor-core GEMM
        cudaFuncSetAttribute(gemm_kernel,
                             cudaFuncAttributeMaxDynamicSharedMemorySize,
                             SMEM_TOTAL);
        dim3 grid(N_PAD / BN, M_TOT / BM);   // (38, 32)
        gemm_kernel<<<grid, 512, SMEM_TOTAL>>>(b, out);
    }
}

// round 8
// speedup vs baseline: 1.8889x; 1.0244x over previous
#include <cuda_runtime.h>
#include <cuda_fp16.h>
#include <cstdint>

// LoRAConv1D: out = x @ W + b + 4.0 * (x @ A) @ B
//   x:[8192,1600]f32  W:[1600,4800]f32  b:[4800]  A:[1600,8]  B:[8,4800]
//
// Single-product fp16 tensor path (sm_103 non-'a' target):
//  1) W' = W + 4*A@B rounded fp16, transposed [N,K], N padded 4800->4864
//  2) x rounded fp16 [M,K]
//  3) out = fp16(x)*fp16(W') + b, fp32 accum via mma.sync m16n8k16
//     (calibrated rel err 2.93e-4 < 1e-3)
//  GEMM: BM=256 BN=128 BK=64, 512 threads (16 warps), warp tile 64x32,
//  4-stage cp.async (48KB/stage), 128B-pitch SW128 swizzle,
//  B-fragment software pipelining incl. cross-iteration prefetch.

#define M_TOT 8192
#define N_TOT 4800
#define N_PAD 4864
#define K_TOT 1600
#define RANK  8

#define BM 256
#define BN 128
#define BK 64
#define KITERS (K_TOT / BK)        // 25

// stage layout (bytes): A[256*128] B[128*128]
#define A_OFF 0
#define B_OFF 32768
#define STAGE_BYTES 49152
#define SMEM_TOTAL (4 * STAGE_BYTES)   // 196608

// ---------------- device scratch (static, alloc-free) ----------------------
__device__ __half g_x[(size_t)M_TOT * K_TOT];    // fp16 x
__device__ __half g_w[(size_t)N_PAD * K_TOT];    // [N_PAD,K] fp16 W' (pad=0)

// ---------------- helpers ---------------------------------------------------
__device__ __forceinline__ uint32_t smem_u32(const void* p) {
    uint32_t a;
    asm("{ .reg .u64 t; cvta.to.shared.u64 t, %1; cvt.u32.u64 %0, t; }"
        : "=r"(a) : "l"(p));
    return a;
}
// 128B-pitch SW128 swizzle: 16B chunk ch of row -> ch ^ (row & 7).
__device__ __forceinline__ uint32_t swz128(int row, int ch) {
    return (uint32_t)(row * 128 + 16 * (ch ^ (row & 7)));
}
__device__ __forceinline__ void cp16(uint32_t dst, const void* src) {
    asm volatile("cp.async.cg.shared.global [%0], [%1], 16;"
                 :: "r"(dst), "l"(src));
}
#define CP_COMMIT() asm volatile("cp.async.commit_group;")
#define CP_WAIT2()  asm volatile("cp.async.wait_group 2;")

__device__ __forceinline__ void ldm_x4(uint32_t* r, uint32_t addr) {
    asm volatile("ldmatrix.sync.aligned.m8n8.x4.shared.b16 {%0,%1,%2,%3}, [%4];"
                 : "=r"(r[0]), "=r"(r[1]), "=r"(r[2]), "=r"(r[3]) : "r"(addr));
}
__device__ __forceinline__ void mma_f16(float* d, const uint32_t* a,
                                        const uint32_t* b) {
    asm volatile(
        "mma.sync.aligned.m16n8k16.row.col.f32.f16.f16.f32 "
        "{%0,%1,%2,%3}, {%4,%5,%6,%7}, {%8,%9}, {%0,%1,%2,%3};"
        : "+f"(d[0]), "+f"(d[1]), "+f"(d[2]), "+f"(d[3])
        : "r"(a[0]), "r"(a[1]), "r"(a[2]), "r"(a[3]), "r"(b[0]), "r"(b[1]));
}

// ---------------- kernel 1: x -> fp16 ---------------------------------------
__global__ void convert_x_kernel(const float* __restrict__ x) {
    size_t base = ((size_t)blockIdx.x * blockDim.x + threadIdx.x) * 8;
    if (base >= (size_t)M_TOT * K_TOT) return;
    float v[8];
    *(float4*)(v)     = *(const float4*)(x + base);
    *(float4*)(v + 4) = *(const float4*)(x + base + 4);
    uint4 ph;
    __half* hp = (__half*)&ph;
#pragma unroll
    for (int j = 0; j < 8; j++) hp[j] = __float2half_rn(v[j]);
    *(uint4*)((char*)g_x + base * 2) = ph;
}

// ---------------- kernel 2: W' = W + 4*A@B -> fp16, transposed [N_PAD,K] ----
__global__ void fuse_w_kernel(const float* __restrict__ W,
                              const float* __restrict__ A,
                              const float* __restrict__ Bl) {
    __shared__ __half sh[32][33];
    const int n0 = blockIdx.x * 32, k0 = blockIdx.y * 32;
    const int tx = threadIdx.x & 31, ty = threadIdx.x >> 5;   // 32 x 8
#pragma unroll
    for (int rr = 0; rr < 4; rr++) {
        int k = k0 + ty + rr * 8, n = n0 + tx;
        float acc = W[(size_t)k * N_TOT + n];
#pragma unroll
        for (int r = 0; r < RANK; r++)
            acc += 4.0f * A[k * RANK + r] * Bl[r * N_TOT + n];
        sh[ty + rr * 8][tx] = __float2half_rn(acc);
    }
    __syncthreads();
#pragma unroll
    for (int rr = 0; rr < 4; rr++) {
        int n = n0 + ty + rr * 8, k = k0 + tx;
        g_w[(size_t)n * K_TOT + k] = sh[tx][ty + rr * 8];
    }
}

// ---------------- kernel 3: fp16 mma.sync GEMM ------------------------------
// 16 warps: wm = wid&3 (64-row slab), wn = wid>>2 (32-col slab).
// Warp tile 64x32: mt=4 (m16), nt=4 (n8) -> acc[4][4][4] = 64 regs.
__global__ __launch_bounds__(512, 1)
void gemm_kernel(const float* __restrict__ bias, float* __restrict__ out) {
    extern __shared__ char smem[];
    const uint32_t sb = smem_u32(smem);
    const int tid = threadIdx.x, lane = tid & 31, wid = tid >> 5;
    const int wm = wid & 3;
    const int wn = wid >> 2;
    const int m0 = blockIdx.y * BM;
    const int n0 = blockIdx.x * BN;
    const uint32_t l7 = lane & 7;

    // ---- fragment base addresses (row*128); chunk XOR applied per kk ----
    uint32_t aBase[4];
#pragma unroll
    for (int mt = 0; mt < 4; mt++)
        aBase[mt] = A_OFF + (uint32_t)(wm * 64 + mt * 16 + (lane & 15)) * 128;
    uint32_t bBase[2];
#pragma unroll
    for (int p = 0; p < 2; p++)
        bBase[p] = B_OFF +
            (uint32_t)(wn * 32 + (2 * p + ((lane >> 4) & 1)) * 8 + l7) * 128;
    const uint32_t aSel = lane >> 4;          // A k-half from bit 4
    const uint32_t bSel = (lane >> 3) & 1;    // B k-half from bit 3

    float acc[4][4][4];
#pragma unroll
    for (int i = 0; i < 4; i++)
#pragma unroll
        for (int j = 0; j < 4; j++)
#pragma unroll
            for (int k = 0; k < 4; k++) acc[i][j][k] = 0.0f;

    // ---- stage loader: A 2048 + B 1024 chunks of 16B over 512 threads -----
    auto load_stage = [&](int s, int k0) {
        const uint32_t st = sb + s * STAGE_BYTES;
#pragma unroll
        for (int i = 0; i < 4; i++) {
            int idx = tid + i * 512;
            int row = idx >> 3, ch = idx & 7;
            cp16(st + A_OFF + swz128(row, ch),
                 g_x + (size_t)(m0 + row) * K_TOT + k0 + ch * 8);
        }
#pragma unroll
        for (int i = 0; i < 2; i++) {
            int idx = tid + i * 512;
            int row = idx >> 3, ch = idx & 7;
            cp16(st + B_OFF + swz128(row, ch),
                 g_w + (size_t)(n0 + row) * K_TOT + k0 + ch * 8);
        }
    };

    // xor chunk offsets for fragment loads at k-step kk
    auto xA = [&](int kk) { return 16u * (((uint32_t)(kk * 2) + aSel) ^ l7); };
    auto xB = [&](int kk) { return 16u * (((uint32_t)(kk * 2) + bSel) ^ l7); };

    // ---- prologue: fill 3 stages ----
    load_stage(0, 0);       CP_COMMIT();
    load_stage(1, BK);      CP_COMMIT();
    load_stage(2, 2 * BK);  CP_COMMIT();
    CP_WAIT2();             // stage 0 complete
    __syncthreads();

    // B fragments double buffer; preload iter0 kk0
    uint32_t bf[2][2][4];
    {
        const uint32_t st0 = sb + 0 * STAGE_BYTES;
#pragma unroll
        for (int p = 0; p < 2; p++) ldm_x4(bf[0][p], st0 + bBase[p] + xB(0));
    }

    // ---- mainloop ----
    for (int t = 0; t < KITERS; t++) {
        const uint32_t st = sb + (t & 3) * STAGE_BYTES;

        // issue load of stage t+3 (overwrites slot (t-1)&3, protected by the
        // barrier at the end of the previous iteration)
        if (t + 3 < KITERS) load_stage((t + 3) & 3, (t + 3) * BK);
        CP_COMMIT();

#pragma unroll
        for (int kk = 0; kk < 4; kk++) {
            const int cb = kk & 1, nb = cb ^ 1;
            uint32_t a[4][4];
#pragma unroll
            for (int mt = 0; mt < 4; mt++)
                ldm_x4(a[mt], st + aBase[mt] + xA(kk));
            if (kk < 3) {                     // prefetch next kk's B frags
#pragma unroll
                for (int p = 0; p < 2; p++)
                    ldm_x4(bf[nb][p], st + bBase[p] + xB(kk + 1));
            }
#pragma unroll
            for (int mt = 0; mt < 4; mt++)
#pragma unroll
                for (int p = 0; p < 2; p++) {
                    mma_f16(acc[mt][2 * p],     a[mt], &bf[cb][p][0]);
                    mma_f16(acc[mt][2 * p + 1], a[mt], &bf[cb][p][2]);
                }
        }

        CP_WAIT2();                           // stage t+1 landed
        if (t + 1 < KITERS) {
            // cross-iteration prefetch: kk0 B frags of stage t+1.
            // Safe before the barrier: reads stage (t+1)&3, while the next
            // iteration's writes target stage (t+3)&3 != (t+1)&3.
            const uint32_t stn = sb + ((t + 1) & 3) * STAGE_BYTES;
#pragma unroll
            for (int p = 0; p < 2; p++)
                ldm_x4(bf[0][p], stn + bBase[p] + xB(0));
        }
        __syncthreads();                      // all reads of stage t done
    }

    // ---- epilogue: add bias, float2 stores (guard N edge: pad 4800..4863) --
    const int r0 = lane >> 2, c0 = (lane & 3) * 2;
#pragma unroll
    for (int mt = 0; mt < 4; mt++)
#pragma unroll
        for (int nt = 0; nt < 4; nt++) {
            const int col = n0 + wn * 32 + nt * 8 + c0;
            if (col < N_TOT) {
                const float bx = bias[col], by = bias[col + 1];
#pragma unroll
                for (int h = 0; h < 2; h++) {
                    const int row = m0 + wm * 64 + mt * 16 + r0 + h * 8;
                    float2 v;
                    v.x = acc[mt][nt][h * 2 + 0] + bx;
                    v.y = acc[mt][nt][h * 2 + 1] + by;
                    *(float2*)(out + (size_t)row * N_TOT + col) = v;
                }
            }
        }
}

// ---------------------------------------------------------------------------
extern "C" void kernel_launch(void* const* d_in, const int* in_sizes, int n_in,
                              void* d_out, int out_size) {
    const float* x  = (const float*)d_in[0];
    const float* W  = (const float*)d_in[1];
    const float* b  = (const float*)d_in[2];
    const float* lA = (const float*)d_in[3];
    const float* lB = (const float*)d_in[4];
    float* out = (float*)d_out;
    (void)in_sizes; (void)n_in; (void)out_size;

    {   // x -> fp16
        size_t total = (size_t)M_TOT * K_TOT / 8;
        convert_x_kernel<<<(unsigned)((total + 255) / 256), 256>>>(x);
    }
    {   // fuse LoRA + round + transpose W (pad rows 4800..4863 stay zero)
        dim3 grid(N_TOT / 32, K_TOT / 32);
        fuse_w_kernel<<<grid, 256>>>(W, lA, lB);
    }
    {   // fp16 tensor-core GEMM
        cudaFuncSetAttribute(gemm_kernel,
                             cudaFuncAttributeMaxDynamicSharedMemorySize,
                             SMEM_TOTAL);
        dim3 grid(N_PAD / BN, M_TOT / BM);   // (38, 32)
        gemm_kernel<<<grid, 512, SMEM_TOTAL>>>(b, out);
    }
}